// round 16
// baseline (speedup 1.0000x reference)
#include <cuda_runtime.h>
#include <cuda_bf16.h>
#include <cuda_fp16.h>
#include <cstdint>
#include <cstddef>

// ============================================================
// Problem constants
// ============================================================
#define NN   100000      // nodes
#define NE   1600000     // edges
#define NP   100096      // padded: 128*782 = 64*1564
#define NB128 782        // gemm0 row tiles (128 rows)
#define NB64  1564       // s8 GEMM row tiles (64 rows)
#define D    256
#define DH   128
#define SCAN_BLKS 98     // ceil(NN / 1024)

// ============================================================
// Device global scratch (no cudaMalloc allowed)
// ============================================================
__device__ __align__(256) int8_t g_h1[(size_t)NP * D];  // activations int8 hi plane
__device__ __align__(256) int8_t g_h0[(size_t)NP * D];  // activations int8 lo plane
__device__ __align__(256) float g_a[(size_t)NP * DH];   // relu(x@W2^T + b2)
__device__ __align__(256) float g_y[(size_t)NP * DH];   // x@W3^T fp32 (layer 1)
__device__ __align__(256) __half g_yh[(size_t)NP * DH]; // x@W3^T fp16 (layer 2)
__device__ __align__(256) __nv_bfloat16 g_w1hi[D * D],  g_w1lo[D * D];
__device__ __align__(256) int8_t g_w2q1[DH * D], g_w2q0[DH * D];
__device__ __align__(256) int8_t g_w3q1[DH * D], g_w3q0[DH * D];
__device__ __align__(256) int8_t g_wd1q1[D * D], g_wd1q0[D * D];
__device__ __align__(256) int g_rowptr[NN + 1];
__device__ __align__(256) int g_cursor[NN];
__device__ __align__(256) int g_cnt[NN];
__device__ __align__(256) int g_colidx[NE];
__device__ __align__(256) int g_bsum[128];
__device__ __align__(256) int g_boff[128];
__device__ int g_is64;

// ============================================================
// Helpers
// ============================================================
__device__ __forceinline__ uint32_t smem_u32(const void* p) {
    uint32_t a;
    asm("{ .reg .u64 t; cvta.to.shared.u64 t, %1; cvt.u32.u64 %0, t; }"
        : "=r"(a) : "l"(p));
    return a;
}

#define SW128(o) ((o) ^ (((o) >> 3) & 0x70))

__device__ __forceinline__ void cp16(uint32_t dst, const void* src) {
    asm volatile("cp.async.cg.shared.global [%0], [%1], 16;" :: "r"(dst), "l"(src));
}
__device__ __forceinline__ void cp_commit() {
    asm volatile("cp.async.commit_group;" ::: "memory");
}
template <int N>
__device__ __forceinline__ void cp_wait() {
    asm volatile("cp.async.wait_group %0;" :: "n"(N) : "memory");
}

__device__ __forceinline__ void ldsm4(uint32_t* r, uint32_t addr) {
    asm volatile("ldmatrix.sync.aligned.m8n8.x4.shared.b16 {%0,%1,%2,%3}, [%4];"
        : "=r"(r[0]), "=r"(r[1]), "=r"(r[2]), "=r"(r[3]) : "r"(addr));
}

__device__ __forceinline__ void mma_bf16(float* c, const uint32_t* a,
                                         uint32_t b0, uint32_t b1) {
    asm volatile(
        "mma.sync.aligned.m16n8k16.row.col.f32.bf16.bf16.f32 "
        "{%0,%1,%2,%3}, {%4,%5,%6,%7}, {%8,%9}, {%0,%1,%2,%3};"
        : "+f"(c[0]), "+f"(c[1]), "+f"(c[2]), "+f"(c[3])
        : "r"(a[0]), "r"(a[1]), "r"(a[2]), "r"(a[3]), "r"(b0), "r"(b1));
}
// int8 K=32 MMA, s32 accumulate (fragments byte-identical to f16 k16 frags)
__device__ __forceinline__ void mma_s8(int* c, const uint32_t* a,
                                       uint32_t b0, uint32_t b1) {
    asm volatile(
        "mma.sync.aligned.m16n8k32.row.col.s32.s8.s8.s32 "
        "{%0,%1,%2,%3}, {%4,%5,%6,%7}, {%8,%9}, {%0,%1,%2,%3};"
        : "+r"(c[0]), "+r"(c[1]), "+r"(c[2]), "+r"(c[3])
        : "r"(a[0]), "r"(a[1]), "r"(a[2]), "r"(a[3]), "r"(b0), "r"(b1));
}

__device__ __forceinline__ void split_bf(float v, __nv_bfloat16& h, __nv_bfloat16& l) {
    h = __float2bfloat16(v);
    l = __float2bfloat16(v - __bfloat162float(h));
}
__device__ __forceinline__ uint32_t pack2(__nv_bfloat16 a, __nv_bfloat16 b) {
    __nv_bfloat162 t; t.x = a; t.y = b;
    return *reinterpret_cast<uint32_t*>(&t);
}
__device__ __forceinline__ uint32_t pack2h(__half a, __half b) {
    __half2 t; t.x = a; t.y = b;
    return *reinterpret_cast<uint32_t*>(&t);
}
__device__ __forceinline__ uint32_t pack4i8(int a, int b, int c, int d) {
    return (uint32_t)(a & 255) | ((uint32_t)(b & 255) << 8)
         | ((uint32_t)(c & 255) << 16) | ((uint32_t)(d & 255) << 24);
}
// value*S = q1 + q0/256 (+eps); q1,q0 in int8 range
__device__ __forceinline__ void quant2(float v, float S, int& q1, int& q0) {
    float t = v * S;
    float h = rintf(t);
    float l = rintf((t - h) * 256.0f);
    if (l > 127.f) l = 127.f;
    if (l < -128.f) l = -128.f;
    q1 = (int)h; q0 = (int)l;
}
// decode scale: A = h*127*256, B = w*127*16*256 -> h*w = (65536*chi+256*cmid)*INVS
static constexpr float INVS = 1.0f / (16129.0f * 1048576.0f);   // 127^2 * 16 * 65536

// ============================================================
// Weight conversion: W1 -> bf16 hi/lo ; W2/W3/Wd1 -> int8 2-plane
// ============================================================
__global__ void conv_w_all_kernel(const float* __restrict__ W1,
                                  const float* __restrict__ W2,
                                  const float* __restrict__ W3,
                                  const float* __restrict__ Wd1) {
    int i = blockIdx.x * blockDim.x + threadIdx.x;
    if (i >= 49152) return;
    if (i < 16384) {
        float4 v = __ldg(((const float4*)W1) + i);
        __nv_bfloat16 h0, l0, h1, l1, h2, l2, h3, l3;
        split_bf(v.x, h0, l0); split_bf(v.y, h1, l1);
        split_bf(v.z, h2, l2); split_bf(v.w, h3, l3);
        ((uint2*)g_w1hi)[i] = make_uint2(pack2(h0, h1), pack2(h2, h3));
        ((uint2*)g_w1lo)[i] = make_uint2(pack2(l0, l1), pack2(l2, l3));
        return;
    }
    const float* w; int8_t *p1, *p0; int off;
    if (i < 24576)      { w = W2;  p1 = g_w2q1;  p0 = g_w2q0;  off = i - 16384; }
    else if (i < 32768) { w = W3;  p1 = g_w3q1;  p0 = g_w3q0;  off = i - 24576; }
    else                { w = Wd1; p1 = g_wd1q1; p0 = g_wd1q0; off = i - 32768; }
    float4 v = __ldg(((const float4*)w) + off);
    int a1, a0, b1, b0, c1, c0, d1, d0;
    quant2(v.x, 2032.0f, a1, a0);   // 127*16
    quant2(v.y, 2032.0f, b1, b0);
    quant2(v.z, 2032.0f, c1, c0);
    quant2(v.w, 2032.0f, d1, d0);
    ((uint32_t*)p1)[off] = pack4i8(a1, b1, c1, d1);
    ((uint32_t*)p0)[off] = pack4i8(a0, b0, c0, d0);
}

// ============================================================
// CSR build chain (side stream — all kernels wide or tiny-regs)
// ============================================================
__global__ void zero_cnt_kernel() {
    int i = blockIdx.x * blockDim.x + threadIdx.x;
    if (i < NN) g_cnt[i] = 0;
}

__global__ void detect_kernel(const int* __restrict__ ei) {
    int z = 1;
    for (int i = 0; i < 64; i++)
        if (ei[2 * i + 1] != 0) { z = 0; break; }
    g_is64 = z;
}

__global__ void count_kernel(const int* __restrict__ ei) {
    int e = blockIdx.x * blockDim.x + threadIdx.x;
    if (e >= NE) return;
    int d = g_is64 ? __ldg(&ei[2 * ((size_t)NE + e)]) : __ldg(&ei[NE + e]);
    if ((unsigned)d < NN) atomicAdd(&g_cnt[d], 1);
}

__global__ void scan_block_kernel() {
    __shared__ int sd[1024];
    int t = threadIdx.x;
    int i = blockIdx.x * 1024 + t;
    sd[t] = (i < NN) ? g_cnt[i] : 0;
    __syncthreads();
    #pragma unroll
    for (int off = 512; off > 0; off >>= 1) {
        if (t < off) sd[t] += sd[t + off];
        __syncthreads();
    }
    if (t == 0) g_bsum[blockIdx.x] = sd[0];
}

__global__ void scan_top_kernel() {
    __shared__ int sd[128];
    int t = threadIdx.x;
    sd[t] = (t < SCAN_BLKS) ? g_bsum[t] : 0;
    __syncthreads();
    if (t == 0) {
        int run = 0;
        for (int b = 0; b < SCAN_BLKS; b++) {
            g_boff[b] = run;
            run += sd[b];
        }
        g_rowptr[NN] = run;
    }
}

__global__ void scan_apply_kernel() {
    __shared__ int sd[1024];
    int t = threadIdx.x;
    int i = blockIdx.x * 1024 + t;
    int v = (i < NN) ? g_cnt[i] : 0;
    sd[t] = v;
    __syncthreads();
    #pragma unroll
    for (int off = 1; off < 1024; off <<= 1) {
        int add = (t >= off) ? sd[t - off] : 0;
        __syncthreads();
        sd[t] += add;
        __syncthreads();
    }
    if (i < NN) {
        int excl = sd[t] - v + g_boff[blockIdx.x];
        g_rowptr[i] = excl;
        g_cursor[i] = excl;
    }
}

__global__ void fill_edges_kernel(const int* __restrict__ ei) {
    int e = blockIdx.x * blockDim.x + threadIdx.x;
    if (e >= NE) return;
    int s, d;
    if (g_is64) {
        s = __ldg(&ei[2 * e]);
        d = __ldg(&ei[2 * ((size_t)NE + e)]);
    } else {
        s = __ldg(&ei[e]);
        d = __ldg(&ei[NE + e]);
    }
    if ((unsigned)s < NN && (unsigned)d < NN) {
        int p = atomicAdd(&g_cursor[d], 1);
        g_colidx[p] = s;
    }
}

// ============================================================
// Layer-1 GEMM (bf16 3-pass exact) with FUSED x fp32->bf16 hi/lo
// conversion. CTA 128x256, 8 warps (2x4), warp tile 64x64.
// Epilogue: relu(+b1), l2norm, quantize to int8 2-plane g_h1/g_h0.
// ============================================================
static constexpr int G0_AH  = 0;
static constexpr int G0_AL  = 16384;
static constexpr int G0_XR  = 32768;
static constexpr int G0_B0  = 65536;
static constexpr int G0_B1  = 131072;
static constexpr int G0_SMEM = 196608;
static constexpr int SSTRIDE = 260;

__global__ void __launch_bounds__(256, 1)
gemm0_kernel(const float* __restrict__ x, const float* __restrict__ bias) {
    extern __shared__ char smem[];
    uint32_t sb = smem_u32(smem);
    int tid = threadIdx.x, wid = tid >> 5, lane = tid & 31;
    int rowbase = blockIdx.x * 128;
    int wrow = wid & 1;
    int wcol = wid >> 1;

    float c[4][8][4];
    #pragma unroll
    for (int mt = 0; mt < 4; mt++)
        #pragma unroll
        for (int nt = 0; nt < 8; nt++)
            #pragma unroll
            for (int q = 0; q < 4; q++) c[mt][nt][q] = 0.f;

    int q8 = lane >> 3, l8 = lane & 7;

    auto issue_x = [&](int kb) {
        for (int t = tid; t < 2048; t += 256) {
            int r = t >> 4, g = t & 15;
            int gr = rowbase + r; if (gr >= NN) gr = NN - 1;
            cp16(sb + G0_XR + (uint32_t)(r * 256 + g * 16),
                 x + (size_t)gr * D + kb + g * 4);
        }
    };
    auto issue_B = [&](int st, int kb) {
        uint32_t bh = sb + (st ? G0_B1 : G0_B0);
        for (int t = tid; t < 2048; t += 256) {
            int r = t >> 3, g = t & 7;
            uint32_t so = SW128((uint32_t)(r * 128 + g * 16));
            size_t ob = ((size_t)r * D + kb + g * 8) * 2;
            cp16(bh + so,         (const uint8_t*)g_w1hi + ob);
            cp16(bh + 32768 + so, (const uint8_t*)g_w1lo + ob);
        }
    };

    issue_x(0); issue_B(0, 0); cp_commit();

    for (int ch = 0; ch < 4; ch++) {
        cp_wait<0>();
        __syncthreads();
        #pragma unroll
        for (int j = 0; j < 8; j++) {
            int idx = tid + j * 256;
            float4 v = reinterpret_cast<const float4*>(smem + G0_XR)[idx];
            int r = idx >> 4, g4 = idx & 15;
            uint32_t bo = (uint32_t)(r * 128 + g4 * 8);
            uint32_t so = bo ^ ((bo >> 3) & 0x70);
            __nv_bfloat16 h0, l0, h1, l1, h2, l2, h3, l3;
            split_bf(v.x, h0, l0); split_bf(v.y, h1, l1);
            split_bf(v.z, h2, l2); split_bf(v.w, h3, l3);
            *reinterpret_cast<uint2*>(smem + G0_AH + so) = make_uint2(pack2(h0, h1), pack2(h2, h3));
            *reinterpret_cast<uint2*>(smem + G0_AL + so) = make_uint2(pack2(l0, l1), pack2(l2, l3));
        }
        __syncthreads();
        if (ch < 3) { issue_x((ch + 1) * 64); issue_B((ch + 1) & 1, (ch + 1) * 64); cp_commit(); }

        uint32_t bbh = sb + ((ch & 1) ? G0_B1 : G0_B0);
        #pragma unroll
        for (int ks = 0; ks < 4; ks++) {
            uint32_t ah[4][4], al[4][4];
            #pragma unroll
            for (int mt = 0; mt < 4; mt++) {
                int row = wrow * 64 + mt * 16 + (q8 & 1) * 8 + l8;
                uint32_t off = SW128((uint32_t)(row * 128 + ks * 32 + (q8 >> 1) * 16));
                ldsm4(ah[mt], sb + G0_AH + off);
                ldsm4(al[mt], sb + G0_AL + off);
            }
            #pragma unroll
            for (int nt = 0; nt < 4; nt++) {
                int nrow = wcol * 64 + nt * 16 + ((q8 >> 1) & 1) * 8 + l8;
                uint32_t off = SW128((uint32_t)(nrow * 128 + ks * 32 + (q8 & 1) * 16));
                uint32_t bh[4], bl[4];
                ldsm4(bh, bbh + off);
                ldsm4(bl, bbh + 32768 + off);
                #pragma unroll
                for (int mt = 0; mt < 4; mt++) {
                    mma_bf16(c[mt][nt * 2],     ah[mt], bh[0], bh[1]);
                    mma_bf16(c[mt][nt * 2],     ah[mt], bl[0], bl[1]);
                    mma_bf16(c[mt][nt * 2],     al[mt], bh[0], bh[1]);
                    mma_bf16(c[mt][nt * 2 + 1], ah[mt], bh[2], bh[3]);
                    mma_bf16(c[mt][nt * 2 + 1], ah[mt], bl[2], bl[3]);
                    mma_bf16(c[mt][nt * 2 + 1], al[mt], bh[2], bh[3]);
                }
            }
        }
        __syncthreads();
    }

    float* stage = reinterpret_cast<float*>(smem);
    #pragma unroll
    for (int mt = 0; mt < 4; mt++)
        #pragma unroll
        for (int nt = 0; nt < 8; nt++) {
            int r0  = wrow * 64 + mt * 16 + (lane >> 2);
            int col = wcol * 64 + nt * 8 + 2 * (lane & 3);
            float* p = stage + r0 * SSTRIDE + col;
            p[0] = c[mt][nt][0];
            p[1] = c[mt][nt][1];
            p[8 * SSTRIDE]     = c[mt][nt][2];
            p[8 * SSTRIDE + 1] = c[mt][nt][3];
        }
    __syncthreads();

    for (int r = wid; r < 128; r += 8) {
        int gr = rowbase + r;
        bool ok = gr < NN;
        const float* rowp = stage + r * SSTRIDE + lane * 8;
        int cb = lane * 8;
        float v[8];
        float ss = 0.f;
        #pragma unroll
        for (int j = 0; j < 8; j++) {
            v[j] = fmaxf(rowp[j] + __ldg(&bias[cb + j]), 0.f);
            ss += v[j] * v[j];
        }
        #pragma unroll
        for (int off = 16; off >= 1; off >>= 1)
            ss += __shfl_xor_sync(0xffffffffu, ss, off);
        float rn = rsqrtf(ss);
        if (ok) {
            int q1[8], q0[8];
            #pragma unroll
            for (int j = 0; j < 8; j++) quant2(v[j] * rn, 127.0f, q1[j], q0[j]);
            *reinterpret_cast<uint2*>(g_h1 + (size_t)gr * D + cb) =
                make_uint2(pack4i8(q1[0], q1[1], q1[2], q1[3]),
                           pack4i8(q1[4], q1[5], q1[6], q1[7]));
            *reinterpret_cast<uint2*>(g_h0 + (size_t)gr * D + cb) =
                make_uint2(pack4i8(q0[0], q0[1], q0[2], q0[3]),
                           pack4i8(q0[4], q0[5], q0[6], q0[7]));
        }
    }
}

// ============================================================
// int8 N=256 GEMM: CTA 64x256, 8 warps (2 row x 4 col),
// warp tile 32x64. 3 s8 passes per k32 (H1W1 | H1W0+H0W1).
//  MODE 1: mid, y -> g_y fp32   MODE 3: mid, y -> g_yh fp16
//  MODE 2: final head -> out
// smem/stage: A1 8K | A0 8K | B1 32K | B0 32K  (x2 stages)
// ============================================================
static constexpr int S8_A1 = 0;
static constexpr int S8_A0 = 8192;
static constexpr int S8_B1 = 16384;
static constexpr int S8_B0 = 49152;
static constexpr int S8_STG = 81920;
static constexpr int S8_SMEM = 2 * S8_STG;   // 160 KB

template <int MODE>
__global__ void __launch_bounds__(256, 1)
gemm_s8_kernel(const float* __restrict__ bias, const float* __restrict__ wd2,
               const float* __restrict__ bd2, float* __restrict__ out) {
    extern __shared__ char smem[];
    uint32_t sb = smem_u32(smem);
    int tid = threadIdx.x, wid = tid >> 5, lane = tid & 31;
    int rowbase = blockIdx.x * 64;
    int wrow = wid & 1;        // 2 x 32 rows
    int wcol = wid >> 1;       // 4 x 64 cols

    const int8_t *B1lo, *B0lo, *B1up, *B0up;
    if (MODE == 1 || MODE == 3) {
        B1lo = g_w2q1; B0lo = g_w2q0; B1up = g_w3q1; B0up = g_w3q0;
    } else {
        B1lo = g_wd1q1; B0lo = g_wd1q0;
        B1up = g_wd1q1 + 128 * D; B0up = g_wd1q0 + 128 * D;
    }

    int chi[2][8][4], cmid[2][8][4];
    #pragma unroll
    for (int mt = 0; mt < 2; mt++)
        #pragma unroll
        for (int nt = 0; nt < 8; nt++)
            #pragma unroll
            for (int q = 0; q < 4; q++) { chi[mt][nt][q] = 0; cmid[mt][nt][q] = 0; }

    int q8 = lane >> 3, l8 = lane & 7;

    auto issue = [&](uint32_t sbuf, int kb) {
        // A planes: 64 rows x 8 x 16B per plane
        for (int t = tid; t < 1024; t += 256) {
            int pl = t >> 9, rr = (t >> 3) & 63, g = t & 7;
            uint32_t so = SW128((uint32_t)(rr * 128 + g * 16));
            const int8_t* src = (pl ? g_h0 : g_h1) + (size_t)(rowbase + rr) * D + kb + g * 16;
            cp16(sbuf + (pl ? S8_A0 : S8_A1) + so, src);
        }
        // B planes: 256 n-rows x 8 x 16B per plane
        for (int t = tid; t < 4096; t += 256) {
            int pl = t >> 11, rr = (t >> 3) & 255, g = t & 7;
            uint32_t so = SW128((uint32_t)(rr * 128 + g * 16));
            int r2 = rr < 128 ? rr : rr - 128;
            const int8_t* base = pl ? (rr < 128 ? B0lo : B0up) : (rr < 128 ? B1lo : B1up);
            cp16(sbuf + (pl ? S8_B0 : S8_B1) + so, base + (size_t)r2 * D + kb + g * 16);
        }
    };

    issue(sb, 0);
    cp_commit();

    for (int ch = 0; ch < 2; ch++) {
        uint32_t buf = sb + (uint32_t)(ch & 1) * S8_STG;
        if (ch < 1) {
            issue(sb + S8_STG, 128);
            cp_commit();
            cp_wait<1>();
        } else {
            cp_wait<0>();
        }
        __syncthreads();

        #pragma unroll
        for (int ks = 0; ks < 4; ks++) {          // k32 steps within k128 chunk
            uint32_t a1[2][4], a0[2][4];
            #pragma unroll
            for (int mt = 0; mt < 2; mt++) {
                int row = wrow * 32 + mt * 16 + (q8 & 1) * 8 + l8;
                uint32_t off = SW128((uint32_t)(row * 128 + ks * 32 + (q8 >> 1) * 16));
                ldsm4(a1[mt], buf + S8_A1 + off);
                ldsm4(a0[mt], buf + S8_A0 + off);
            }
            #pragma unroll
            for (int nt = 0; nt < 4; nt++) {
                int nrow = wcol * 64 + nt * 16 + ((q8 >> 1) & 1) * 8 + l8;
                uint32_t off = SW128((uint32_t)(nrow * 128 + ks * 32 + (q8 & 1) * 16));
                uint32_t b1[4], b0[4];
                ldsm4(b1, buf + S8_B1 + off);
                ldsm4(b0, buf + S8_B0 + off);
                #pragma unroll
                for (int mt = 0; mt < 2; mt++) {
                    mma_s8(chi [mt][nt * 2],     a1[mt], b1[0], b1[1]);
                    mma_s8(cmid[mt][nt * 2],     a1[mt], b0[0], b0[1]);
                    mma_s8(cmid[mt][nt * 2],     a0[mt], b1[0], b1[1]);
                    mma_s8(chi [mt][nt * 2 + 1], a1[mt], b1[2], b1[3]);
                    mma_s8(cmid[mt][nt * 2 + 1], a1[mt], b0[2], b0[3]);
                    mma_s8(cmid[mt][nt * 2 + 1], a0[mt], b1[2], b1[3]);
                }
            }
        }
        __syncthreads();
    }

    // combine fixed-point terms -> float, stage in smem
    float* stage = reinterpret_cast<float*>(smem);
    #pragma unroll
    for (int mt = 0; mt < 2; mt++)
        #pragma unroll
        for (int nt = 0; nt < 8; nt++) {
            int r0  = wrow * 32 + mt * 16 + (lane >> 2);
            int col = wcol * 64 + nt * 8 + 2 * (lane & 3);
            float* p = stage + r0 * SSTRIDE + col;
            p[0] = ((float)chi[mt][nt][0] * 65536.f + (float)cmid[mt][nt][0] * 256.f) * INVS;
            p[1] = ((float)chi[mt][nt][1] * 65536.f + (float)cmid[mt][nt][1] * 256.f) * INVS;
            p[8 * SSTRIDE]     = ((float)chi[mt][nt][2] * 65536.f + (float)cmid[mt][nt][2] * 256.f) * INVS;
            p[8 * SSTRIDE + 1] = ((float)chi[mt][nt][3] * 65536.f + (float)cmid[mt][nt][3] * 256.f) * INVS;
        }
    __syncthreads();

    for (int r = wid; r < 64; r += 8) {
        int gr = rowbase + r;
        bool ok = gr < NN;
        const float* rowp = stage + r * SSTRIDE + lane * 8;
        int cb = lane * 8;

        if (MODE == 1 || MODE == 3) {
            float v[8];
            if (lane < 16) {
                #pragma unroll
                for (int j = 0; j < 8; j++)
                    v[j] = fmaxf(rowp[j] + __ldg(&bias[cb + j]), 0.f);
                if (ok) {
                    float4* dst = reinterpret_cast<float4*>(g_a + (size_t)gr * DH + cb);
                    dst[0] = make_float4(v[0], v[1], v[2], v[3]);
                    dst[1] = make_float4(v[4], v[5], v[6], v[7]);
                }
            } else {
                #pragma unroll
                for (int j = 0; j < 8; j++) v[j] = rowp[j];
                if (ok) {
                    if (MODE == 1) {
                        float4* dst = reinterpret_cast<float4*>(g_y + (size_t)gr * DH + (cb - 128));
                        dst[0] = make_float4(v[0], v[1], v[2], v[3]);
                        dst[1] = make_float4(v[4], v[5], v[6], v[7]);
                    } else {
                        __half hh[8];
                        #pragma unroll
                        for (int j = 0; j < 8; j++) hh[j] = __float2half_rn(v[j]);
                        *reinterpret_cast<uint4*>(g_yh + (size_t)gr * DH + (cb - 128)) =
                            make_uint4(pack2h(hh[0], hh[1]), pack2h(hh[2], hh[3]),
                                       pack2h(hh[4], hh[5]), pack2h(hh[6], hh[7]));
                    }
                }
            }
        } else {
            float acc = 0.f;
            #pragma unroll
            for (int j = 0; j < 8; j++) {
                float vv = fmaxf(rowp[j] + __ldg(&bias[cb + j]), 0.f);
                acc += vv * __ldg(&wd2[cb + j]);
            }
            #pragma unroll
            for (int off = 16; off >= 1; off >>= 1)
                acc += __shfl_xor_sync(0xffffffffu, acc, off);
            if (lane == 0 && ok) out[gr] = acc + __ldg(bd2);
        }
    }
}

// ============================================================
// Fused CSR gather-reduce + bias + relu + l2norm + int8 store
// One warp per dst node; lane owns 4 cols of each 128-wide half.
// YH=0: gather fp32 g_y (layer 1)  YH=1: gather fp16 g_yh (layer 2)
// ============================================================
template <int YH>
__global__ void agg_combine_kernel(const float* __restrict__ b3) {
    int gw = (blockIdx.x * blockDim.x + threadIdx.x) >> 5;
    int lane = threadIdx.x & 31;
    if (gw >= NN) return;
    int n = gw;
    int beg = __ldg(&g_rowptr[n]);
    int end = __ldg(&g_rowptr[n + 1]);

    float ax = 0.f, ay = 0.f, az = 0.f, aw = 0.f;
    int i = beg;
    if (YH == 0) {
        for (; i + 4 <= end; i += 4) {
            int s0 = __ldg(&g_colidx[i]);
            int s1 = __ldg(&g_colidx[i + 1]);
            int s2 = __ldg(&g_colidx[i + 2]);
            int s3 = __ldg(&g_colidx[i + 3]);
            float4 v0 = __ldg(reinterpret_cast<const float4*>(g_y + (size_t)s0 * DH) + lane);
            float4 v1 = __ldg(reinterpret_cast<const float4*>(g_y + (size_t)s1 * DH) + lane);
            float4 v2 = __ldg(reinterpret_cast<const float4*>(g_y + (size_t)s2 * DH) + lane);
            float4 v3 = __ldg(reinterpret_cast<const float4*>(g_y + (size_t)s3 * DH) + lane);
            ax += (v0.x + v1.x) + (v2.x + v3.x);
            ay += (v0.y + v1.y) + (v2.y + v3.y);
            az += (v0.z + v1.z) + (v2.z + v3.z);
            aw += (v0.w + v1.w) + (v2.w + v3.w);
        }
        for (; i < end; i++) {
            int s = __ldg(&g_colidx[i]);
            float4 v = __ldg(reinterpret_cast<const float4*>(g_y + (size_t)s * DH) + lane);
            ax += v.x; ay += v.y; az += v.z; aw += v.w;
        }
    } else {
        for (; i + 4 <= end; i += 4) {
            int s0 = __ldg(&g_colidx[i]);
            int s1 = __ldg(&g_colidx[i + 1]);
            int s2 = __ldg(&g_colidx[i + 2]);
            int s3 = __ldg(&g_colidx[i + 3]);
            uint2 u0 = __ldg(reinterpret_cast<const uint2*>(g_yh + (size_t)s0 * DH) + lane);
            uint2 u1 = __ldg(reinterpret_cast<const uint2*>(g_yh + (size_t)s1 * DH) + lane);
            uint2 u2 = __ldg(reinterpret_cast<const uint2*>(g_yh + (size_t)s2 * DH) + lane);
            uint2 u3 = __ldg(reinterpret_cast<const uint2*>(g_yh + (size_t)s3 * DH) + lane);
            float2 a0 = __half22float2(*reinterpret_cast<__half2*>(&u0.x));
            float2 b0 = __half22float2(*reinterpret_cast<__half2*>(&u0.y));
            float2 a1 = __half22float2(*reinterpret_cast<__half2*>(&u1.x));
            float2 b1 = __half22float2(*reinterpret_cast<__half2*>(&u1.y));
            float2 a2 = __half22float2(*reinterpret_cast<__half2*>(&u2.x));
            float2 b2 = __half22float2(*reinterpret_cast<__half2*>(&u2.y));
            float2 a3 = __half22float2(*reinterpret_cast<__half2*>(&u3.x));
            float2 b3v = __half22float2(*reinterpret_cast<__half2*>(&u3.y));
            ax += (a0.x + a1.x) + (a2.x + a3.x);
            ay += (a0.y + a1.y) + (a2.y + a3.y);
            az += (b0.x + b1.x) + (b2.x + b3v.x);
            aw += (b0.y + b1.y) + (b2.y + b3v.y);
        }
        for (; i < end; i++) {
            int s = __ldg(&g_colidx[i]);
            uint2 u = __ldg(reinterpret_cast<const uint2*>(g_yh + (size_t)s * DH) + lane);
            float2 a0 = __half22float2(*reinterpret_cast<__half2*>(&u.x));
            float2 b0 = __half22float2(*reinterpret_cast<__half2*>(&u.y));
            ax += a0.x; ay += a0.y; az += b0.x; aw += b0.y;
        }
    }

    float4 av = __ldg(reinterpret_cast<const float4*>(g_a + (size_t)n * DH) + lane);
    float4 bb = __ldg(reinterpret_cast<const float4*>(b3) + lane);
    float m0 = fmaxf(ax + bb.x, 0.f);
    float m1 = fmaxf(ay + bb.y, 0.f);
    float m2 = fmaxf(az + bb.z, 0.f);
    float m3 = fmaxf(aw + bb.w, 0.f);

    float ss = av.x * av.x + av.y * av.y + av.z * av.z + av.w * av.w
             + m0 * m0 + m1 * m1 + m2 * m2 + m3 * m3;
    #pragma unroll
    for (int off = 16; off >= 1; off >>= 1)
        ss += __shfl_xor_sync(0xffffffffu, ss, off);
    float rn = rsqrtf(ss);

    size_t base = (size_t)n * D;
    {
        int q1[4], q0[4];
        quant2(av.x * rn, 127.0f, q1[0], q0[0]);
        quant2(av.y * rn, 127.0f, q1[1], q0[1]);
        quant2(av.z * rn, 127.0f, q1[2], q0[2]);
        quant2(av.w * rn, 127.0f, q1[3], q0[3]);
        *reinterpret_cast<uint32_t*>(g_h1 + base + lane * 4) = pack4i8(q1[0], q1[1], q1[2], q1[3]);
        *reinterpret_cast<uint32_t*>(g_h0 + base + lane * 4) = pack4i8(q0[0], q0[1], q0[2], q0[3]);
    }
    {
        int q1[4], q0[4];
        quant2(m0 * rn, 127.0f, q1[0], q0[0]);
        quant2(m1 * rn, 127.0f, q1[1], q0[1]);
        quant2(m2 * rn, 127.0f, q1[2], q0[2]);
        quant2(m3 * rn, 127.0f, q1[3], q0[3]);
        *reinterpret_cast<uint32_t*>(g_h1 + base + 128 + lane * 4) = pack4i8(q1[0], q1[1], q1[2], q1[3]);
        *reinterpret_cast<uint32_t*>(g_h0 + base + 128 + lane * 4) = pack4i8(q0[0], q0[1], q0[2], q0[3]);
    }
}

// ============================================================
// Host launcher — CSR chain on side stream overlapping main chain
// ============================================================
static cudaStream_t s2 = nullptr;
static cudaEvent_t evFork, evCSR;

extern "C" void kernel_launch(void* const* d_in, const int* in_sizes, int n_in,
                              void* d_out, int out_size) {
    const float* x   = (const float*)d_in[0];
    const int*   ei  = (const int*)d_in[1];    // int32 or int64 (auto-detected)
    const float* W1  = (const float*)d_in[2];
    const float* b1  = (const float*)d_in[3];
    const float* W2  = (const float*)d_in[4];
    const float* b2  = (const float*)d_in[5];
    const float* W3  = (const float*)d_in[6];
    const float* b3  = (const float*)d_in[7];
    const float* Wd1 = (const float*)d_in[8];
    const float* bd1 = (const float*)d_in[9];
    const float* Wd2 = (const float*)d_in[10];
    const float* bd2 = (const float*)d_in[11];
    float* out = (float*)d_out;

    if (!s2) {
        cudaStreamCreateWithFlags(&s2, cudaStreamNonBlocking);
        cudaEventCreateWithFlags(&evFork, cudaEventDisableTiming);
        cudaEventCreateWithFlags(&evCSR,  cudaEventDisableTiming);
        cudaFuncSetAttribute(gemm0_kernel,      cudaFuncAttributeMaxDynamicSharedMemorySize, G0_SMEM);
        cudaFuncSetAttribute(gemm_s8_kernel<1>, cudaFuncAttributeMaxDynamicSharedMemorySize, S8_SMEM);
        cudaFuncSetAttribute(gemm_s8_kernel<2>, cudaFuncAttributeMaxDynamicSharedMemorySize, S8_SMEM);
        cudaFuncSetAttribute(gemm_s8_kernel<3>, cudaFuncAttributeMaxDynamicSharedMemorySize, S8_SMEM);
    }

    // ---- fork side stream: full CSR build
    cudaEventRecord(evFork, 0);
    cudaStreamWaitEvent(s2, evFork, 0);
    zero_cnt_kernel<<<(NN + 255) / 256, 256, 0, s2>>>();
    detect_kernel<<<1, 1, 0, s2>>>(ei);
    count_kernel<<<(NE + 255) / 256, 256, 0, s2>>>(ei);
    scan_block_kernel<<<SCAN_BLKS, 1024, 0, s2>>>();
    scan_top_kernel<<<1, 128, 0, s2>>>();
    scan_apply_kernel<<<SCAN_BLKS, 1024, 0, s2>>>();
    fill_edges_kernel<<<(NE + 255) / 256, 256, 0, s2>>>(ei);
    cudaEventRecord(evCSR, s2);

    // ---- main stream
    conv_w_all_kernel<<<192, 256>>>(W1, W2, W3, Wd1);
    gemm0_kernel<<<NB128, 256, G0_SMEM>>>(x, b1);

    // conv layer 1 (fp32 y)
    gemm_s8_kernel<1><<<NB64, 256, S8_SMEM>>>(b2, nullptr, nullptr, nullptr);
    cudaStreamWaitEvent(0, evCSR, 0);
    agg_combine_kernel<0><<<(NN * 32 + 255) / 256, 256>>>(b3);

    // conv layer 2 (fp16 y)
    gemm_s8_kernel<3><<<NB64, 256, S8_SMEM>>>(b2, nullptr, nullptr, nullptr);
    agg_combine_kernel<1><<<(NN * 32 + 255) / 256, 256>>>(b3);

    // head
    gemm_s8_kernel<2><<<NB64, 256, S8_SMEM>>>(bd1, Wd2, bd2, out);
}

// round 17
// speedup vs baseline: 2.2386x; 2.2386x over previous
#include <cuda_runtime.h>
#include <cuda_bf16.h>
#include <cuda_fp16.h>
#include <cstdint>
#include <cstddef>

// ============================================================
// Problem constants
// ============================================================
#define NN   100000      // nodes
#define NE   1600000     // edges
#define NP   100096      // padded: 128*782
#define NB128 782        // GEMM row tiles (128 rows each)
#define D    256
#define DH   128
#define SCAN_BLKS 98     // ceil(NN / 1024)

// ============================================================
// Device global scratch (no cudaMalloc allowed)
// ============================================================
__device__ __align__(256) __half g_h[(size_t)NP * D];   // activations (fp16)
__device__ __align__(256) float g_a[(size_t)NP * DH];   // relu(x@W2^T + b2)
__device__ __align__(256) __half g_yh[(size_t)NP * DH]; // x@W3^T fp16 (both layers)
__device__ __align__(256) __nv_bfloat16 g_w1hi[D * D],  g_w1lo[D * D];
__device__ __align__(256) __half g_w2hi[DH * D], g_w2lo[DH * D];   // lo scaled x1024
__device__ __align__(256) __half g_w3hi[DH * D], g_w3lo[DH * D];   // lo scaled x1024
__device__ __align__(256) __half g_wd1hi[D * D], g_wd1lo[D * D];   // lo scaled x1024
__device__ __align__(256) int g_rowptr[NN + 1];
__device__ __align__(256) int g_cursor[NN];
__device__ __align__(256) int g_cnt[NN];
__device__ __align__(256) int g_colidx[NE];
__device__ __align__(256) int g_bsum[128];
__device__ __align__(256) int g_boff[128];
__device__ int g_is64;

// ============================================================
// Helpers
// ============================================================
__device__ __forceinline__ uint32_t smem_u32(const void* p) {
    uint32_t a;
    asm("{ .reg .u64 t; cvta.to.shared.u64 t, %1; cvt.u32.u64 %0, t; }"
        : "=r"(a) : "l"(p));
    return a;
}

#define SW128(o) ((o) ^ (((o) >> 3) & 0x70))

__device__ __forceinline__ void cp16(uint32_t dst, const void* src) {
    asm volatile("cp.async.cg.shared.global [%0], [%1], 16;" :: "r"(dst), "l"(src));
}
__device__ __forceinline__ void cp_commit() {
    asm volatile("cp.async.commit_group;" ::: "memory");
}
template <int N>
__device__ __forceinline__ void cp_wait() {
    asm volatile("cp.async.wait_group %0;" :: "n"(N) : "memory");
}

__device__ __forceinline__ void ldsm4(uint32_t* r, uint32_t addr) {
    asm volatile("ldmatrix.sync.aligned.m8n8.x4.shared.b16 {%0,%1,%2,%3}, [%4];"
        : "=r"(r[0]), "=r"(r[1]), "=r"(r[2]), "=r"(r[3]) : "r"(addr));
}

__device__ __forceinline__ void mma_bf16(float* c, const uint32_t* a,
                                         uint32_t b0, uint32_t b1) {
    asm volatile(
        "mma.sync.aligned.m16n8k16.row.col.f32.bf16.bf16.f32 "
        "{%0,%1,%2,%3}, {%4,%5,%6,%7}, {%8,%9}, {%0,%1,%2,%3};"
        : "+f"(c[0]), "+f"(c[1]), "+f"(c[2]), "+f"(c[3])
        : "r"(a[0]), "r"(a[1]), "r"(a[2]), "r"(a[3]), "r"(b0), "r"(b1));
}
__device__ __forceinline__ void mma_f16(float* c, const uint32_t* a,
                                        uint32_t b0, uint32_t b1) {
    asm volatile(
        "mma.sync.aligned.m16n8k16.row.col.f32.f16.f16.f32 "
        "{%0,%1,%2,%3}, {%4,%5,%6,%7}, {%8,%9}, {%0,%1,%2,%3};"
        : "+f"(c[0]), "+f"(c[1]), "+f"(c[2]), "+f"(c[3])
        : "r"(a[0]), "r"(a[1]), "r"(a[2]), "r"(a[3]), "r"(b0), "r"(b1));
}
// f16 accumulator variant (2 f16x2 regs) — used for the lo pass
__device__ __forceinline__ void mma_f16h(uint32_t* c2, const uint32_t* a,
                                         uint32_t b0, uint32_t b1) {
    asm volatile(
        "mma.sync.aligned.m16n8k16.row.col.f16.f16.f16.f16 "
        "{%0,%1}, {%2,%3,%4,%5}, {%6,%7}, {%0,%1};"
        : "+r"(c2[0]), "+r"(c2[1])
        : "r"(a[0]), "r"(a[1]), "r"(a[2]), "r"(a[3]), "r"(b0), "r"(b1));
}

__device__ __forceinline__ void split_bf(float v, __nv_bfloat16& h, __nv_bfloat16& l) {
    h = __float2bfloat16(v);
    l = __float2bfloat16(v - __bfloat162float(h));
}
__device__ __forceinline__ uint32_t pack2(__nv_bfloat16 a, __nv_bfloat16 b) {
    __nv_bfloat162 t; t.x = a; t.y = b;
    return *reinterpret_cast<uint32_t*>(&t);
}
__device__ __forceinline__ uint32_t pack2h(__half a, __half b) {
    __half2 t; t.x = a; t.y = b;
    return *reinterpret_cast<uint32_t*>(&t);
}

// ============================================================
// Weight conversion (one kernel)
// W1 -> bf16 hi/lo ; W2/W3/Wd1 -> fp16 hi + (lo * 1024) fp16
// ============================================================
__global__ void conv_w_all_kernel(const float* __restrict__ W1,
                                  const float* __restrict__ W2,
                                  const float* __restrict__ W3,
                                  const float* __restrict__ Wd1) {
    int i = blockIdx.x * blockDim.x + threadIdx.x;
    if (i >= 49152) return;
    if (i < 16384) {
        float4 v = __ldg(((const float4*)W1) + i);
        __nv_bfloat16 h0, l0, h1, l1, h2, l2, h3, l3;
        split_bf(v.x, h0, l0); split_bf(v.y, h1, l1);
        split_bf(v.z, h2, l2); split_bf(v.w, h3, l3);
        ((uint2*)g_w1hi)[i] = make_uint2(pack2(h0, h1), pack2(h2, h3));
        ((uint2*)g_w1lo)[i] = make_uint2(pack2(l0, l1), pack2(l2, l3));
        return;
    }
    const float* w; __half *hi, *lo; int off;
    if (i < 24576)      { w = W2;  hi = g_w2hi;  lo = g_w2lo;  off = i - 16384; }
    else if (i < 32768) { w = W3;  hi = g_w3hi;  lo = g_w3lo;  off = i - 24576; }
    else                { w = Wd1; hi = g_wd1hi; lo = g_wd1lo; off = i - 32768; }
    float4 v = __ldg(((const float4*)w) + off);
    __half h0 = __float2half_rn(v.x), h1 = __float2half_rn(v.y);
    __half h2 = __float2half_rn(v.z), h3 = __float2half_rn(v.w);
    __half l0 = __float2half_rn((v.x - __half2float(h0)) * 1024.0f);
    __half l1 = __float2half_rn((v.y - __half2float(h1)) * 1024.0f);
    __half l2 = __float2half_rn((v.z - __half2float(h2)) * 1024.0f);
    __half l3 = __float2half_rn((v.w - __half2float(h3)) * 1024.0f);
    ((uint2*)hi)[off] = make_uint2(pack2h(h0, h1), pack2h(h2, h3));
    ((uint2*)lo)[off] = make_uint2(pack2h(l0, l1), pack2h(l2, l3));
}

// ============================================================
// CSR build chain (side stream — all kernels wide or tiny-regs)
// ============================================================
__global__ void zero_cnt_kernel() {
    int i = blockIdx.x * blockDim.x + threadIdx.x;
    if (i < NN) g_cnt[i] = 0;
}

__global__ void detect_kernel(const int* __restrict__ ei) {
    int z = 1;
    for (int i = 0; i < 64; i++)
        if (ei[2 * i + 1] != 0) { z = 0; break; }
    g_is64 = z;
}

__global__ void count_kernel(const int* __restrict__ ei) {
    int e = blockIdx.x * blockDim.x + threadIdx.x;
    if (e >= NE) return;
    int d = g_is64 ? __ldg(&ei[2 * ((size_t)NE + e)]) : __ldg(&ei[NE + e]);
    if ((unsigned)d < NN) atomicAdd(&g_cnt[d], 1);
}

__global__ void scan_block_kernel() {          // grid SCAN_BLKS, block 1024
    __shared__ int sd[1024];
    int t = threadIdx.x;
    int i = blockIdx.x * 1024 + t;
    sd[t] = (i < NN) ? g_cnt[i] : 0;
    __syncthreads();
    #pragma unroll
    for (int off = 512; off > 0; off >>= 1) {
        if (t < off) sd[t] += sd[t + off];
        __syncthreads();
    }
    if (t == 0) g_bsum[blockIdx.x] = sd[0];
}

__global__ void scan_top_kernel() {            // 1 block, 128 threads (small regs)
    __shared__ int sd[128];
    int t = threadIdx.x;
    sd[t] = (t < SCAN_BLKS) ? g_bsum[t] : 0;
    __syncthreads();
    if (t == 0) {
        int run = 0;
        for (int b = 0; b < SCAN_BLKS; b++) {
            g_boff[b] = run;
            run += sd[b];
        }
        g_rowptr[NN] = run;
    }
}

__global__ void scan_apply_kernel() {          // grid SCAN_BLKS, block 1024
    __shared__ int sd[1024];
    int t = threadIdx.x;
    int i = blockIdx.x * 1024 + t;
    int v = (i < NN) ? g_cnt[i] : 0;
    sd[t] = v;
    __syncthreads();
    #pragma unroll
    for (int off = 1; off < 1024; off <<= 1) {
        int add = (t >= off) ? sd[t - off] : 0;
        __syncthreads();
        sd[t] += add;
        __syncthreads();
    }
    if (i < NN) {
        int excl = sd[t] - v + g_boff[blockIdx.x];
        g_rowptr[i] = excl;
        g_cursor[i] = excl;
    }
}

__global__ void fill_edges_kernel(const int* __restrict__ ei) {
    int e = blockIdx.x * blockDim.x + threadIdx.x;
    if (e >= NE) return;
    int s, d;
    if (g_is64) {
        s = __ldg(&ei[2 * e]);
        d = __ldg(&ei[2 * ((size_t)NE + e)]);
    } else {
        s = __ldg(&ei[e]);
        d = __ldg(&ei[NE + e]);
    }
    if ((unsigned)s < NN && (unsigned)d < NN) {
        int p = atomicAdd(&g_cursor[d], 1);
        g_colidx[p] = s;
    }
}

// ============================================================
// Layer-1 GEMM (bf16 3-pass exact) with FUSED x fp32->bf16 hi/lo
// conversion. CTA 128x256, 8 warps (2x4), warp tile 64x64.
// smem: AH 16K | AL 16K | XRAW 32K | BH0 32K | BL0 32K | BH1 32K | BL1 32K
// ============================================================
static constexpr int G0_AH  = 0;
static constexpr int G0_AL  = 16384;
static constexpr int G0_XR  = 32768;
static constexpr int G0_B0  = 65536;     // BH0; BL0 at +32768
static constexpr int G0_B1  = 131072;    // BH1; BL1 at +32768
static constexpr int G0_SMEM = 196608;
static constexpr int SSTRIDE = 260;

__global__ void __launch_bounds__(256, 1)
gemm0_kernel(const float* __restrict__ x, const float* __restrict__ bias) {
    extern __shared__ char smem[];
    uint32_t sb = smem_u32(smem);
    int tid = threadIdx.x, wid = tid >> 5, lane = tid & 31;
    int rowbase = blockIdx.x * 128;
    int wrow = wid & 1;
    int wcol = wid >> 1;

    float c[4][8][4];
    #pragma unroll
    for (int mt = 0; mt < 4; mt++)
        #pragma unroll
        for (int nt = 0; nt < 8; nt++)
            #pragma unroll
            for (int q = 0; q < 4; q++) c[mt][nt][q] = 0.f;

    int q8 = lane >> 3, l8 = lane & 7;

    auto issue_x = [&](int kb) {
        for (int t = tid; t < 2048; t += 256) {
            int r = t >> 4, g = t & 15;
            int gr = rowbase + r; if (gr >= NN) gr = NN - 1;   // pad rows masked later
            cp16(sb + G0_XR + (uint32_t)(r * 256 + g * 16),
                 x + (size_t)gr * D + kb + g * 4);
        }
    };
    auto issue_B = [&](int st, int kb) {
        uint32_t bh = sb + (st ? G0_B1 : G0_B0);
        for (int t = tid; t < 2048; t += 256) {
            int r = t >> 3, g = t & 7;
            uint32_t so = SW128((uint32_t)(r * 128 + g * 16));
            size_t ob = ((size_t)r * D + kb + g * 8) * 2;
            cp16(bh + so,         (const uint8_t*)g_w1hi + ob);
            cp16(bh + 32768 + so, (const uint8_t*)g_w1lo + ob);
        }
    };

    issue_x(0); issue_B(0, 0); cp_commit();

    for (int ch = 0; ch < 4; ch++) {
        cp_wait<0>();
        __syncthreads();
        #pragma unroll
        for (int j = 0; j < 8; j++) {
            int idx = tid + j * 256;
            float4 v = reinterpret_cast<const float4*>(smem + G0_XR)[idx];
            int r = idx >> 4, g4 = idx & 15;
            uint32_t bo = (uint32_t)(r * 128 + g4 * 8);
            uint32_t so = bo ^ ((bo >> 3) & 0x70);
            __nv_bfloat16 h0, l0, h1, l1, h2, l2, h3, l3;
            split_bf(v.x, h0, l0); split_bf(v.y, h1, l1);
            split_bf(v.z, h2, l2); split_bf(v.w, h3, l3);
            *reinterpret_cast<uint2*>(smem + G0_AH + so) = make_uint2(pack2(h0, h1), pack2(h2, h3));
            *reinterpret_cast<uint2*>(smem + G0_AL + so) = make_uint2(pack2(l0, l1), pack2(l2, l3));
        }
        __syncthreads();
        if (ch < 3) { issue_x((ch + 1) * 64); issue_B((ch + 1) & 1, (ch + 1) * 64); cp_commit(); }

        uint32_t bbh = sb + ((ch & 1) ? G0_B1 : G0_B0);
        #pragma unroll
        for (int ks = 0; ks < 4; ks++) {
            uint32_t ah[4][4], al[4][4];
            #pragma unroll
            for (int mt = 0; mt < 4; mt++) {
                int row = wrow * 64 + mt * 16 + (q8 & 1) * 8 + l8;
                uint32_t off = SW128((uint32_t)(row * 128 + ks * 32 + (q8 >> 1) * 16));
                ldsm4(ah[mt], sb + G0_AH + off);
                ldsm4(al[mt], sb + G0_AL + off);
            }
            #pragma unroll
            for (int nt = 0; nt < 4; nt++) {
                int nrow = wcol * 64 + nt * 16 + ((q8 >> 1) & 1) * 8 + l8;
                uint32_t off = SW128((uint32_t)(nrow * 128 + ks * 32 + (q8 & 1) * 16));
                uint32_t bh[4], bl[4];
                ldsm4(bh, bbh + off);
                ldsm4(bl, bbh + 32768 + off);
                #pragma unroll
                for (int mt = 0; mt < 4; mt++) {
                    mma_bf16(c[mt][nt * 2],     ah[mt], bh[0], bh[1]);
                    mma_bf16(c[mt][nt * 2],     ah[mt], bl[0], bl[1]);
                    mma_bf16(c[mt][nt * 2],     al[mt], bh[0], bh[1]);
                    mma_bf16(c[mt][nt * 2 + 1], ah[mt], bh[2], bh[3]);
                    mma_bf16(c[mt][nt * 2 + 1], ah[mt], bl[2], bl[3]);
                    mma_bf16(c[mt][nt * 2 + 1], al[mt], bh[2], bh[3]);
                }
            }
        }
        __syncthreads();
    }

    float* stage = reinterpret_cast<float*>(smem);
    #pragma unroll
    for (int mt = 0; mt < 4; mt++)
        #pragma unroll
        for (int nt = 0; nt < 8; nt++) {
            int r0  = wrow * 64 + mt * 16 + (lane >> 2);
            int col = wcol * 64 + nt * 8 + 2 * (lane & 3);
            float* p = stage + r0 * SSTRIDE + col;
            p[0] = c[mt][nt][0];
            p[1] = c[mt][nt][1];
            p[8 * SSTRIDE]     = c[mt][nt][2];
            p[8 * SSTRIDE + 1] = c[mt][nt][3];
        }
    __syncthreads();

    for (int r = wid; r < 128; r += 8) {
        int gr = rowbase + r;
        bool ok = gr < NN;
        const float* rowp = stage + r * SSTRIDE + lane * 8;
        int cb = lane * 8;
        float v[8];
        float ss = 0.f;
        #pragma unroll
        for (int j = 0; j < 8; j++) {
            v[j] = fmaxf(rowp[j] + __ldg(&bias[cb + j]), 0.f);
            ss += v[j] * v[j];
        }
        #pragma unroll
        for (int off = 16; off >= 1; off >>= 1)
            ss += __shfl_xor_sync(0xffffffffu, ss, off);
        float rn = rsqrtf(ss);
        if (ok) {
            __half h[8];
            #pragma unroll
            for (int j = 0; j < 8; j++) h[j] = __float2half_rn(v[j] * rn);
            *reinterpret_cast<uint4*>(g_h + (size_t)gr * D + cb) =
                make_uint4(pack2h(h[0], h[1]), pack2h(h[2], h[3]),
                           pack2h(h[4], h[5]), pack2h(h[6], h[7]));
        }
    }
}

// ============================================================
// fp16 N=256 GEMM: CTA 128x256, hi pass f32-acc + lo pass
// f16-acc (lo plane pre-scaled x1024).
//  MODE 1: mid, a -> g_a fp32, y -> g_yh fp16 (both conv layers)
//  MODE 2: final head -> out
// ============================================================
static constexpr int F_OF_BH = 16384;
static constexpr int F_OF_BL = 49152;
static constexpr int F_STG   = 81920;
static constexpr int F_SMEM  = 2 * F_STG;

template <int MODE>
__global__ void __launch_bounds__(256, 1)
gemm_kernel(const float* __restrict__ bias, const float* __restrict__ wd2,
            const float* __restrict__ bd2, float* __restrict__ out) {
    extern __shared__ char smem[];
    uint32_t sb = smem_u32(smem);
    int tid = threadIdx.x, wid = tid >> 5, lane = tid & 31;
    int rowbase = blockIdx.x * 128;
    int wrow = wid & 1;
    int wcol = wid >> 1;

    const uint8_t *BloH, *BloL, *BupH, *BupL;
    if (MODE == 1) {
        BloH = (const uint8_t*)g_w2hi;  BloL = (const uint8_t*)g_w2lo;
        BupH = (const uint8_t*)g_w3hi;  BupL = (const uint8_t*)g_w3lo;
    } else {
        BloH = (const uint8_t*)g_wd1hi; BloL = (const uint8_t*)g_wd1lo;
        BupH = (const uint8_t*)(g_wd1hi + 128 * D); BupL = (const uint8_t*)(g_wd1lo + 128 * D);
    }

    float c[4][8][4];
    uint32_t c16[4][8][2];
    #pragma unroll
    for (int mt = 0; mt < 4; mt++)
        #pragma unroll
        for (int nt = 0; nt < 8; nt++) {
            #pragma unroll
            for (int q = 0; q < 4; q++) c[mt][nt][q] = 0.f;
            c16[mt][nt][0] = 0u; c16[mt][nt][1] = 0u;
        }

    int q8 = lane >> 3, l8 = lane & 7;

    auto issue = [&](uint32_t sbuf, int kb) {
        for (int t = tid; t < 1024; t += 256) {
            int r = t >> 3, g = t & 7;
            uint32_t so = SW128((uint32_t)(r * 128 + g * 16));
            cp16(sbuf + so,
                 (const uint8_t*)g_h + ((size_t)(rowbase + r) * D + kb + g * 8) * 2);
        }
        for (int t = tid; t < 2048; t += 256) {
            int r = t >> 3, g = t & 7;
            uint32_t so = SW128((uint32_t)(r * 128 + g * 16));
            size_t ob = ((size_t)(r < 128 ? r : r - 128) * D + kb + g * 8) * 2;
            cp16(sbuf + F_OF_BH + so, (r < 128 ? BloH : BupH) + ob);
            cp16(sbuf + F_OF_BL + so, (r < 128 ? BloL : BupL) + ob);
        }
    };

    issue(sb, 0);
    cp_commit();

    for (int ch = 0; ch < 4; ch++) {
        uint32_t buf = sb + (uint32_t)(ch & 1) * F_STG;
        if (ch < 3) {
            issue(sb + (uint32_t)((ch + 1) & 1) * F_STG, (ch + 1) * 64);
            cp_commit();
            cp_wait<1>();
        } else {
            cp_wait<0>();
        }
        __syncthreads();

        #pragma unroll
        for (int ks = 0; ks < 4; ks++) {
            uint32_t ah[4][4];
            #pragma unroll
            for (int mt = 0; mt < 4; mt++) {
                int row = wrow * 64 + mt * 16 + (q8 & 1) * 8 + l8;
                uint32_t off = SW128((uint32_t)(row * 128 + ks * 32 + (q8 >> 1) * 16));
                ldsm4(ah[mt], buf + off);
            }
            #pragma unroll
            for (int nt = 0; nt < 4; nt++) {
                int nrow = wcol * 64 + nt * 16 + ((q8 >> 1) & 1) * 8 + l8;
                uint32_t off = SW128((uint32_t)(nrow * 128 + ks * 32 + (q8 & 1) * 16));
                uint32_t bh[4], bl[4];
                ldsm4(bh, buf + F_OF_BH + off);
                ldsm4(bl, buf + F_OF_BL + off);
                #pragma unroll
                for (int mt = 0; mt < 4; mt++) {
                    mma_f16 (c[mt][nt * 2],       ah[mt], bh[0], bh[1]);   // hi, f32 acc
                    mma_f16 (c[mt][nt * 2 + 1],   ah[mt], bh[2], bh[3]);
                    mma_f16h(c16[mt][nt * 2],     ah[mt], bl[0], bl[1]);   // lo, f16 acc
                    mma_f16h(c16[mt][nt * 2 + 1], ah[mt], bl[2], bl[3]);
                }
            }
        }
        __syncthreads();
    }

    const float INV = 1.0f / 1024.0f;
    #pragma unroll
    for (int mt = 0; mt < 4; mt++)
        #pragma unroll
        for (int nt = 0; nt < 8; nt++) {
            __half2 p0 = *reinterpret_cast<__half2*>(&c16[mt][nt][0]);
            __half2 p1 = *reinterpret_cast<__half2*>(&c16[mt][nt][1]);
            c[mt][nt][0] += __low2float(p0) * INV;
            c[mt][nt][1] += __high2float(p0) * INV;
            c[mt][nt][2] += __low2float(p1) * INV;
            c[mt][nt][3] += __high2float(p1) * INV;
        }

    float* stage = reinterpret_cast<float*>(smem);
    #pragma unroll
    for (int mt = 0; mt < 4; mt++)
        #pragma unroll
        for (int nt = 0; nt < 8; nt++) {
            int r0  = wrow * 64 + mt * 16 + (lane >> 2);
            int col = wcol * 64 + nt * 8 + 2 * (lane & 3);
            float* p = stage + r0 * SSTRIDE + col;
            p[0] = c[mt][nt][0];
            p[1] = c[mt][nt][1];
            p[8 * SSTRIDE]     = c[mt][nt][2];
            p[8 * SSTRIDE + 1] = c[mt][nt][3];
        }
    __syncthreads();

    for (int r = wid; r < 128; r += 8) {
        int gr = rowbase + r;
        bool ok = gr < NN;
        const float* rowp = stage + r * SSTRIDE + lane * 8;
        int cb = lane * 8;

        if (MODE == 1) {
            float v[8];
            if (lane < 16) {
                #pragma unroll
                for (int j = 0; j < 8; j++)
                    v[j] = fmaxf(rowp[j] + __ldg(&bias[cb + j]), 0.f);
                if (ok) {
                    float4* dst = reinterpret_cast<float4*>(g_a + (size_t)gr * DH + cb);
                    dst[0] = make_float4(v[0], v[1], v[2], v[3]);
                    dst[1] = make_float4(v[4], v[5], v[6], v[7]);
                }
            } else {
                #pragma unroll
                for (int j = 0; j < 8; j++) v[j] = rowp[j];
                if (ok) {
                    __half hh[8];
                    #pragma unroll
                    for (int j = 0; j < 8; j++) hh[j] = __float2half_rn(v[j]);
                    *reinterpret_cast<uint4*>(g_yh + (size_t)gr * DH + (cb - 128)) =
                        make_uint4(pack2h(hh[0], hh[1]), pack2h(hh[2], hh[3]),
                                   pack2h(hh[4], hh[5]), pack2h(hh[6], hh[7]));
                }
            }
        } else {
            float acc = 0.f;
            #pragma unroll
            for (int j = 0; j < 8; j++) {
                float vv = fmaxf(rowp[j] + __ldg(&bias[cb + j]), 0.f);
                acc += vv * __ldg(&wd2[cb + j]);
            }
            #pragma unroll
            for (int off = 16; off >= 1; off >>= 1)
                acc += __shfl_xor_sync(0xffffffffu, acc, off);
            if (lane == 0 && ok) out[gr] = acc + __ldg(bd2);
        }
    }
}

// ============================================================
// Fused CSR gather-reduce + bias + relu + l2norm + fp16 store
// One warp per dst node; lane owns 4 cols of each 128-wide half.
// Gathers fp16 g_yh (both layers).
// ============================================================
__global__ void agg_combine_kernel(const float* __restrict__ b3) {
    int gw = (blockIdx.x * blockDim.x + threadIdx.x) >> 5;
    int lane = threadIdx.x & 31;
    if (gw >= NN) return;
    int n = gw;
    int beg = __ldg(&g_rowptr[n]);
    int end = __ldg(&g_rowptr[n + 1]);

    float ax = 0.f, ay = 0.f, az = 0.f, aw = 0.f;
    int i = beg;
    for (; i + 4 <= end; i += 4) {
        int s0 = __ldg(&g_colidx[i]);
        int s1 = __ldg(&g_colidx[i + 1]);
        int s2 = __ldg(&g_colidx[i + 2]);
        int s3 = __ldg(&g_colidx[i + 3]);
        uint2 u0 = __ldg(reinterpret_cast<const uint2*>(g_yh + (size_t)s0 * DH) + lane);
        uint2 u1 = __ldg(reinterpret_cast<const uint2*>(g_yh + (size_t)s1 * DH) + lane);
        uint2 u2 = __ldg(reinterpret_cast<const uint2*>(g_yh + (size_t)s2 * DH) + lane);
        uint2 u3 = __ldg(reinterpret_cast<const uint2*>(g_yh + (size_t)s3 * DH) + lane);
        float2 a0 = __half22float2(*reinterpret_cast<__half2*>(&u0.x));
        float2 b0 = __half22float2(*reinterpret_cast<__half2*>(&u0.y));
        float2 a1 = __half22float2(*reinterpret_cast<__half2*>(&u1.x));
        float2 b1 = __half22float2(*reinterpret_cast<__half2*>(&u1.y));
        float2 a2 = __half22float2(*reinterpret_cast<__half2*>(&u2.x));
        float2 b2 = __half22float2(*reinterpret_cast<__half2*>(&u2.y));
        float2 a3 = __half22float2(*reinterpret_cast<__half2*>(&u3.x));
        float2 b3v = __half22float2(*reinterpret_cast<__half2*>(&u3.y));
        ax += (a0.x + a1.x) + (a2.x + a3.x);
        ay += (a0.y + a1.y) + (a2.y + a3.y);
        az += (b0.x + b1.x) + (b2.x + b3v.x);
        aw += (b0.y + b1.y) + (b2.y + b3v.y);
    }
    for (; i < end; i++) {
        int s = __ldg(&g_colidx[i]);
        uint2 u = __ldg(reinterpret_cast<const uint2*>(g_yh + (size_t)s * DH) + lane);
        float2 a0 = __half22float2(*reinterpret_cast<__half2*>(&u.x));
        float2 b0 = __half22float2(*reinterpret_cast<__half2*>(&u.y));
        ax += a0.x; ay += a0.y; az += b0.x; aw += b0.y;
    }

    float4 av = __ldg(reinterpret_cast<const float4*>(g_a + (size_t)n * DH) + lane);
    float4 bb = __ldg(reinterpret_cast<const float4*>(b3) + lane);
    float m0 = fmaxf(ax + bb.x, 0.f);
    float m1 = fmaxf(ay + bb.y, 0.f);
    float m2 = fmaxf(az + bb.z, 0.f);
    float m3 = fmaxf(aw + bb.w, 0.f);

    float ss = av.x * av.x + av.y * av.y + av.z * av.z + av.w * av.w
             + m0 * m0 + m1 * m1 + m2 * m2 + m3 * m3;
    #pragma unroll
    for (int off = 16; off >= 1; off >>= 1)
        ss += __shfl_xor_sync(0xffffffffu, ss, off);
    float rn = rsqrtf(ss);

    size_t base = (size_t)n * D;
    *reinterpret_cast<uint2*>(g_h + base + lane * 4) =
        make_uint2(pack2h(__float2half_rn(av.x * rn), __float2half_rn(av.y * rn)),
                   pack2h(__float2half_rn(av.z * rn), __float2half_rn(av.w * rn)));
    *reinterpret_cast<uint2*>(g_h + base + 128 + lane * 4) =
        make_uint2(pack2h(__float2half_rn(m0 * rn), __float2half_rn(m1 * rn)),
                   pack2h(__float2half_rn(m2 * rn), __float2half_rn(m3 * rn)));
}

// ============================================================
// Host launcher — CSR chain (wide / tiny-reg kernels) on side
// stream overlapping conv_w + gemm0 + first mid GEMM; joins
// before the first agg_combine.
// ============================================================
static cudaStream_t s2 = nullptr;
static cudaEvent_t evFork, evCSR;

extern "C" void kernel_launch(void* const* d_in, const int* in_sizes, int n_in,
                              void* d_out, int out_size) {
    const float* x   = (const float*)d_in[0];
    const int*   ei  = (const int*)d_in[1];    // int32 or int64 (auto-detected)
    const float* W1  = (const float*)d_in[2];
    const float* b1  = (const float*)d_in[3];
    const float* W2  = (const float*)d_in[4];
    const float* b2  = (const float*)d_in[5];
    const float* W3  = (const float*)d_in[6];
    const float* b3  = (const float*)d_in[7];
    const float* Wd1 = (const float*)d_in[8];
    const float* bd1 = (const float*)d_in[9];
    const float* Wd2 = (const float*)d_in[10];
    const float* bd2 = (const float*)d_in[11];
    float* out = (float*)d_out;

    if (!s2) {
        cudaStreamCreateWithFlags(&s2, cudaStreamNonBlocking);
        cudaEventCreateWithFlags(&evFork, cudaEventDisableTiming);
        cudaEventCreateWithFlags(&evCSR,  cudaEventDisableTiming);
        cudaFuncSetAttribute(gemm0_kernel,   cudaFuncAttributeMaxDynamicSharedMemorySize, G0_SMEM);
        cudaFuncSetAttribute(gemm_kernel<1>, cudaFuncAttributeMaxDynamicSharedMemorySize, F_SMEM);
        cudaFuncSetAttribute(gemm_kernel<2>, cudaFuncAttributeMaxDynamicSharedMemorySize, F_SMEM);
    }

    // ---- fork side stream: full CSR build (independent of main chain)
    cudaEventRecord(evFork, 0);
    cudaStreamWaitEvent(s2, evFork, 0);
    zero_cnt_kernel<<<(NN + 255) / 256, 256, 0, s2>>>();
    detect_kernel<<<1, 1, 0, s2>>>(ei);
    count_kernel<<<(NE + 255) / 256, 256, 0, s2>>>(ei);
    scan_block_kernel<<<SCAN_BLKS, 1024, 0, s2>>>();
    scan_top_kernel<<<1, 128, 0, s2>>>();
    scan_apply_kernel<<<SCAN_BLKS, 1024, 0, s2>>>();
    fill_edges_kernel<<<(NE + 255) / 256, 256, 0, s2>>>(ei);
    cudaEventRecord(evCSR, s2);

    // ---- main stream: weights + layer 1 + first mid GEMM
    conv_w_all_kernel<<<192, 256>>>(W1, W2, W3, Wd1);
    gemm0_kernel<<<NB128, 256, G0_SMEM>>>(x, b1);

    // conv layer 1 (fp16 y)
    gemm_kernel<1><<<NB128, 256, F_SMEM>>>(b2, nullptr, nullptr, nullptr);
    cudaStreamWaitEvent(0, evCSR, 0);          // join CSR before first gather
    agg_combine_kernel<<<(NN * 32 + 255) / 256, 256>>>(b3);

    // conv layer 2 (fp16 y)
    gemm_kernel<1><<<NB128, 256, F_SMEM>>>(b2, nullptr, nullptr, nullptr);
    agg_combine_kernel<<<(NN * 32 + 255) / 256, 256>>>(b3);

    // head: out = relu(h @ Wd1^T + bd1) @ Wd2^T + bd2
    gemm_kernel<2><<<NB128, 256, F_SMEM>>>(bd1, Wd2, bd2, out);
}